// round 1
// baseline (speedup 1.0000x reference)
#include <cuda_runtime.h>
#include <math.h>

// Problem constants
#define B_   512
#define V_   2
#define D_   128
#define M_   1024          // V*B
#define K_   15            // TOP_K
#define KMAX 50
#define INV_T 14.285714285714286f   // 1/0.07

// Scratch (static device globals — no allocation allowed)
__device__ float g_A[M_ * D_];            // anchors, view-major
__device__ float g_nA[M_];                // ||A_i||^2
__device__ float g_G[K_ * B_ * D_];       // gathered neighbors [k][b][d]
__device__ float g_nG[K_ * B_];           // ||G_r||^2
__device__ float g_Pk[K_ * M_ * B_];      // per-k f(dist) partials
__device__ float g_acc[M_ * B_];          // accB
__device__ float g_S[M_ * M_];            // logits_src
__device__ float g_loss[M_];              // per-row loss

// ---------------------------------------------------------------------------
// K1: build anchor matrix A[i= v*B+b][d] = features[b][v][d], plus row norms
__global__ void build_anchor(const float* __restrict__ features) {
    int i = blockIdx.x;            // 0..M-1
    int d = threadIdx.x;           // 0..127
    int v = i >> 9;                // /B_
    int b = i & (B_ - 1);
    float val = features[(b * V_ + v) * D_ + d];
    g_A[i * D_ + d] = val;

    __shared__ float red[D_];
    red[d] = val * val;
    __syncthreads();
    for (int s = D_ / 2; s > 0; s >>= 1) {
        if (d < s) red[d] += red[d + s];
        __syncthreads();
    }
    if (d == 0) g_nA[i] = red[0];
}

// ---------------------------------------------------------------------------
// K2: gather neighbors G[r = k*B+b][d] = saved[rks[indices[b]*KMAX + k]][d]
__global__ void gather_neigh(const float* __restrict__ saved,
                             const int* __restrict__ indices,
                             const int* __restrict__ rks) {
    int r = blockIdx.x;            // 0..K_*B_-1
    int d = threadIdx.x;           // 0..127
    int k = r / B_;
    int b = r - k * B_;
    int idx = rks[indices[b] * KMAX + k];
    float val = saved[(long long)idx * D_ + d];
    g_G[r * D_ + d] = val;

    __shared__ float red[D_];
    red[d] = val * val;
    __syncthreads();
    for (int s = D_ / 2; s > 0; s >>= 1) {
        if (d < s) red[d] += red[d + s];
        __syncthreads();
    }
    if (d == 0) g_nG[r] = red[0];
}

// ---------------------------------------------------------------------------
// K3: Pk[k][i][b] = f(dist(A_i, G[k*B+b]))
// Tiled GEMM-like: 64x64 tile, 256 threads, 4x4 register tile per thread.
#define TI 64
#define TJ 64
#define DC 32
#define SPAD 4

__global__ void __launch_bounds__(256) pk_kernel() {
    __shared__ float As[DC][TI + SPAD];   // transposed: As[d][row]
    __shared__ float Gs[DC][TJ + SPAD];

    int k  = blockIdx.z;
    int i0 = blockIdx.y * TI;
    int b0 = blockIdx.x * TJ;
    int tid = threadIdx.x;
    int tx = tid & 15;
    int ty = tid >> 4;

    const float* Gbase = g_G + k * (B_ * D_);

    float dot[4][4];
#pragma unroll
    for (int a = 0; a < 4; a++)
#pragma unroll
        for (int b = 0; b < 4; b++) dot[a][b] = 0.f;

    for (int dc = 0; dc < D_; dc += DC) {
#pragma unroll
        for (int t = tid; t < TI * DC; t += 256) {
            int r = t >> 5, c = t & 31;
            As[c][r] = g_A[(i0 + r) * D_ + dc + c];
        }
#pragma unroll
        for (int t = tid; t < TJ * DC; t += 256) {
            int r = t >> 5, c = t & 31;
            Gs[c][r] = Gbase[(b0 + r) * D_ + dc + c];
        }
        __syncthreads();
#pragma unroll
        for (int d = 0; d < DC; d++) {
            float4 a4 = *(const float4*)&As[d][ty * 4];
            float4 g4 = *(const float4*)&Gs[d][tx * 4];
            float a[4] = {a4.x, a4.y, a4.z, a4.w};
            float g[4] = {g4.x, g4.y, g4.z, g4.w};
#pragma unroll
            for (int ii = 0; ii < 4; ii++)
#pragma unroll
                for (int jj = 0; jj < 4; jj++)
                    dot[ii][jj] += a[ii] * g[jj];
        }
        __syncthreads();
    }

    int ib = i0 + ty * 4;
    int bb = b0 + tx * 4;
#pragma unroll
    for (int ii = 0; ii < 4; ii++) {
        float na = g_nA[ib + ii];
#pragma unroll
        for (int jj = 0; jj < 4; jj++) {
            float ng = g_nG[k * B_ + bb + jj];
            float sq = na + ng - 2.f * dot[ii][jj];
            sq = fmaxf(sq, 0.f);
            float dd = (sq > 0.f) ? sqrtf(sq) : 0.f;
            float adc = (1.f + 1.f / (1.f + dd)) * INV_T;
            g_Pk[((long long)k * M_ + (ib + ii)) * B_ + bb + jj] = adc;
        }
    }
}

// ---------------------------------------------------------------------------
// K4: accB = mean over k of Pk
__global__ void acc_reduce() {
    int e = blockIdx.x * blockDim.x + threadIdx.x;   // 0..M*B-1
    float s = 0.f;
#pragma unroll
    for (int k = 0; k < K_; k++) s += g_Pk[k * (M_ * B_) + e];
    g_acc[e] = s * (1.f / (float)K_);
}

// ---------------------------------------------------------------------------
// K5: S[i][j] = sqrt(acc[i][j%B]^2 + acc[j][i%B]^2 + f(dist(A_i,A_j))^2)
__global__ void __launch_bounds__(256) s_kernel() {
    __shared__ float As[DC][TI + SPAD];
    __shared__ float Bs[DC][TJ + SPAD];

    int i0 = blockIdx.y * TI;
    int j0 = blockIdx.x * TJ;
    int tid = threadIdx.x;
    int tx = tid & 15;
    int ty = tid >> 4;

    float dot[4][4];
#pragma unroll
    for (int a = 0; a < 4; a++)
#pragma unroll
        for (int b = 0; b < 4; b++) dot[a][b] = 0.f;

    for (int dc = 0; dc < D_; dc += DC) {
#pragma unroll
        for (int t = tid; t < TI * DC; t += 256) {
            int r = t >> 5, c = t & 31;
            As[c][r] = g_A[(i0 + r) * D_ + dc + c];
        }
#pragma unroll
        for (int t = tid; t < TJ * DC; t += 256) {
            int r = t >> 5, c = t & 31;
            Bs[c][r] = g_A[(j0 + r) * D_ + dc + c];
        }
        __syncthreads();
#pragma unroll
        for (int d = 0; d < DC; d++) {
            float4 a4 = *(const float4*)&As[d][ty * 4];
            float4 g4 = *(const float4*)&Bs[d][tx * 4];
            float a[4] = {a4.x, a4.y, a4.z, a4.w};
            float g[4] = {g4.x, g4.y, g4.z, g4.w};
#pragma unroll
            for (int ii = 0; ii < 4; ii++)
#pragma unroll
                for (int jj = 0; jj < 4; jj++)
                    dot[ii][jj] += a[ii] * g[jj];
        }
        __syncthreads();
    }

    int ib = i0 + ty * 4;
    int jb = j0 + tx * 4;
#pragma unroll
    for (int ii = 0; ii < 4; ii++) {
        int i = ib + ii;
        float na = g_nA[i];
        int imod = i & (B_ - 1);
#pragma unroll
        for (int jj = 0; jj < 4; jj++) {
            int j = jb + jj;
            float nb = g_nA[j];
            float sq = na + nb - 2.f * dot[ii][jj];
            sq = fmaxf(sq, 0.f);
            float dd = (sq > 0.f) ? sqrtf(sq) : 0.f;
            float adc = (1.f + 1.f / (1.f + dd)) * INV_T;
            float a1 = g_acc[i * B_ + (j & (B_ - 1))];
            float a2 = g_acc[j * B_ + imod];
            g_S[i * M_ + j] = sqrtf(a1 * a1 + a2 * a2 + adc * adc);
        }
    }
}

// ---------------------------------------------------------------------------
// K6: per-row: max over all j, sumexp over j!=i, one positive at i^B side.
__global__ void __launch_bounds__(256) row_reduce() {
    int i = blockIdx.x;
    int tid = threadIdx.x;
    const float* row = g_S + (long long)i * M_;
    __shared__ float red[256];

    float mx = -1e30f;
    for (int j = tid; j < M_; j += 256) mx = fmaxf(mx, row[j]);
    red[tid] = mx;
    __syncthreads();
    for (int s = 128; s > 0; s >>= 1) {
        if (tid < s) red[tid] = fmaxf(red[tid], red[tid + s]);
        __syncthreads();
    }
    mx = red[0];
    __syncthreads();

    float sum = 0.f;
    for (int j = tid; j < M_; j += 256)
        if (j != i) sum += expf(row[j] - mx);
    red[tid] = sum;
    __syncthreads();
    for (int s = 128; s > 0; s >>= 1) {
        if (tid < s) red[tid] += red[tid + s];
        __syncthreads();
    }
    if (tid == 0) {
        int pos = (i < B_) ? (i + B_) : (i - B_);
        float log_prob = (row[pos] - mx) - logf(red[0]);
        g_loss[i] = -log_prob;    // TEMPERATURE/BASE_TEMPERATURE == 1
    }
}

// ---------------------------------------------------------------------------
// K7: final mean over M rows -> scalar
__global__ void __launch_bounds__(256) final_reduce(float* __restrict__ out) {
    int tid = threadIdx.x;
    __shared__ float red[256];
    float s = 0.f;
    for (int j = tid; j < M_; j += 256) s += g_loss[j];
    red[tid] = s;
    __syncthreads();
    for (int st = 128; st > 0; st >>= 1) {
        if (tid < st) red[tid] += red[tid + st];
        __syncthreads();
    }
    if (tid == 0) out[0] = red[0] * (1.f / (float)M_);
}

// ---------------------------------------------------------------------------
extern "C" void kernel_launch(void* const* d_in, const int* in_sizes, int n_in,
                              void* d_out, int out_size) {
    const float* features = (const float*)d_in[0];   // (512, 2, 128) f32
    const int*   indices  = (const int*)d_in[1];     // (512,) i32
    const float* saved    = (const float*)d_in[2];   // (100000, 128) f32
    const int*   rks      = (const int*)d_in[3];     // (100000, 50) i32
    float* out = (float*)d_out;

    build_anchor<<<M_, D_>>>(features);
    gather_neigh<<<K_ * B_, D_>>>(saved, indices, rks);
    pk_kernel<<<dim3(B_ / TJ, M_ / TI, K_), 256>>>();
    acc_reduce<<<(M_ * B_) / 256, 256>>>();
    s_kernel<<<dim3(M_ / TJ, M_ / TI), 256>>>();
    row_reduce<<<M_, 256>>>();
    final_reduce<<<1, 256>>>(out);
}

// round 2
// speedup vs baseline: 1.4571x; 1.4571x over previous
#include <cuda_runtime.h>
#include <math.h>

// Problem constants
#define B_   512
#define V_   2
#define D_   128
#define M_   1024          // V*B
#define K_   15            // TOP_K
#define KMAX 50
#define INV_T 14.285714285714286f   // 1/0.07

// Scratch (static device globals — no allocation allowed)
__device__ float g_A[M_ * D_];            // anchors, view-major [i][d]
__device__ float g_nA[M_];                // ||A_i||^2 (fp32 exact)
__device__ float g_G[K_ * B_ * D_];       // gathered neighbors [k][b][d]
__device__ float g_nG[K_ * B_];           // ||G_r||^2
__device__ float g_Pk[K_ * M_ * B_];      // per-k f(dist) partials
__device__ float g_acc[M_ * B_];          // accB
__device__ float g_S[M_ * M_];            // logits_src
__device__ float g_loss[M_];              // per-row loss

// ---------------------------------------------------------------------------
__device__ __forceinline__ unsigned f2tf(float x) {
    unsigned r;
    asm("cvt.rna.tf32.f32 %0, %1;" : "=r"(r) : "f"(x));
    return r;
}

__device__ __forceinline__ void mma_tf32(float c[4], const unsigned a[4],
                                         unsigned b0, unsigned b1) {
    asm volatile(
        "mma.sync.aligned.m16n8k8.row.col.f32.tf32.tf32.f32 "
        "{%0,%1,%2,%3}, {%4,%5,%6,%7}, {%8,%9}, {%0,%1,%2,%3};\n"
        : "+f"(c[0]), "+f"(c[1]), "+f"(c[2]), "+f"(c[3])
        : "r"(a[0]), "r"(a[1]), "r"(a[2]), "r"(a[3]), "r"(b0), "r"(b1));
}

__device__ __forceinline__ float fdist(float sq) {
    sq = fmaxf(sq, 0.f);
    float d = (sq > 0.f) ? sqrtf(sq) : 0.f;
    return (1.f + 1.f / (1.f + d)) * INV_T;
}

// ---------------------------------------------------------------------------
// K1: build anchor matrix A[i= v*B+b][d] = features[b][v][d], plus row norms
__global__ void build_anchor(const float* __restrict__ features) {
    int i = blockIdx.x;
    int d = threadIdx.x;
    int v = i >> 9;
    int b = i & (B_ - 1);
    float val = features[(b * V_ + v) * D_ + d];
    g_A[i * D_ + d] = val;

    __shared__ float red[D_];
    red[d] = val * val;
    __syncthreads();
    for (int s = D_ / 2; s > 0; s >>= 1) {
        if (d < s) red[d] += red[d + s];
        __syncthreads();
    }
    if (d == 0) g_nA[i] = red[0];
}

// ---------------------------------------------------------------------------
// K2: gather neighbors G[r = k*B+b][d] = saved[rks[indices[b]*KMAX + k]][d]
__global__ void gather_neigh(const float* __restrict__ saved,
                             const int* __restrict__ indices,
                             const int* __restrict__ rks) {
    int r = blockIdx.x;
    int d = threadIdx.x;
    int k = r / B_;
    int b = r - k * B_;
    int idx = rks[indices[b] * KMAX + k];
    float val = saved[(long long)idx * D_ + d];
    g_G[r * D_ + d] = val;

    __shared__ float red[D_];
    red[d] = val * val;
    __syncthreads();
    for (int s = D_ / 2; s > 0; s >>= 1) {
        if (d < s) red[d] += red[d + s];
        __syncthreads();
    }
    if (d == 0) g_nG[r] = red[0];
}

// ---------------------------------------------------------------------------
// Shared MMA core: computes 128x128 tile of dot(Arows, Brows) with tf32 mma,
// leaves results in c[2][8][4] per thread.
// Block: 256 threads = 8 warps as 4(m) x 2(n). Warp tile 32x64.
// smem: [128 rows][36] tf32 words, row-major, DC=32 per chunk.

#define SROW 36

struct MmaAcc { float c[2][8][4]; };

__device__ __forceinline__ void mma_tile_core(
    const float* __restrict__ Ab,   // 128 rows x 128 d, row stride D_
    const float* __restrict__ Bb,   // 128 rows x 128 d
    unsigned* As, unsigned* Bs,     // [128*SROW] each
    MmaAcc& acc)
{
    int tid = threadIdx.x;
    int lane = tid & 31, warp = tid >> 5;
    int wm = warp >> 1, wn = warp & 1;
    int g = lane >> 2, t4 = lane & 3;

#pragma unroll
    for (int mt = 0; mt < 2; mt++)
#pragma unroll
        for (int nt = 0; nt < 8; nt++)
#pragma unroll
            for (int q = 0; q < 4; q++) acc.c[mt][nt][q] = 0.f;

    for (int dc = 0; dc < D_; dc += 32) {
#pragma unroll
        for (int q = 0; q < 4; q++) {
            int idx = tid + q * 256;      // 0..1023
            int row = idx >> 3;
            int c4 = idx & 7;
            float4 va = *(const float4*)(Ab + row * D_ + dc + c4 * 4);
            unsigned* pa = &As[row * SROW + c4 * 4];
            pa[0] = f2tf(va.x); pa[1] = f2tf(va.y);
            pa[2] = f2tf(va.z); pa[3] = f2tf(va.w);
            float4 vb = *(const float4*)(Bb + row * D_ + dc + c4 * 4);
            unsigned* pb = &Bs[row * SROW + c4 * 4];
            pb[0] = f2tf(vb.x); pb[1] = f2tf(vb.y);
            pb[2] = f2tf(vb.z); pb[3] = f2tf(vb.w);
        }
        __syncthreads();
#pragma unroll
        for (int kk = 0; kk < 32; kk += 8) {
            unsigned a[2][4];
#pragma unroll
            for (int mt = 0; mt < 2; mt++) {
                int r = wm * 32 + mt * 16 + g;
                a[mt][0] = As[r * SROW + kk + t4];
                a[mt][1] = As[(r + 8) * SROW + kk + t4];
                a[mt][2] = As[r * SROW + kk + t4 + 4];
                a[mt][3] = As[(r + 8) * SROW + kk + t4 + 4];
            }
#pragma unroll
            for (int nt = 0; nt < 8; nt++) {
                int col = wn * 64 + nt * 8 + g;
                unsigned b0r = Bs[col * SROW + kk + t4];
                unsigned b1r = Bs[col * SROW + kk + t4 + 4];
#pragma unroll
                for (int mt = 0; mt < 2; mt++)
                    mma_tf32(acc.c[mt][nt], a[mt], b0r, b1r);
            }
        }
        __syncthreads();
    }
}

// ---------------------------------------------------------------------------
// K3: Pk[k][i][b] = f(dist(A_i, G[k*B+b]))  via tf32 mma
__global__ void __launch_bounds__(256, 2) pk_mma() {
    __shared__ unsigned As[128 * SROW];
    __shared__ unsigned Bs[128 * SROW];

    int k = blockIdx.z;
    int i0 = blockIdx.y * 128;
    int b0 = blockIdx.x * 128;
    int tid = threadIdx.x;
    int lane = tid & 31, warp = tid >> 5;
    int wm = warp >> 1, wn = warp & 1;
    int g = lane >> 2, t4 = lane & 3;

    MmaAcc acc;
    mma_tile_core(g_A + i0 * D_, g_G + (k * B_ + b0) * D_, As, Bs, acc);

#pragma unroll
    for (int mt = 0; mt < 2; mt++) {
        int ri = i0 + wm * 32 + mt * 16 + g;
        float na0 = g_nA[ri];
        float na1 = g_nA[ri + 8];
#pragma unroll
        for (int nt = 0; nt < 8; nt++) {
            int cb = b0 + wn * 64 + nt * 8 + 2 * t4;   // local col within B_
            float ng0 = g_nG[k * B_ + cb];
            float ng1 = g_nG[k * B_ + cb + 1];
            float* cc = acc.c[mt][nt];
            float2 v0, v1;
            v0.x = fdist(na0 + ng0 - 2.f * cc[0]);
            v0.y = fdist(na0 + ng1 - 2.f * cc[1]);
            v1.x = fdist(na1 + ng0 - 2.f * cc[2]);
            v1.y = fdist(na1 + ng1 - 2.f * cc[3]);
            *(float2*)&g_Pk[((long long)k * M_ + ri) * B_ + cb] = v0;
            *(float2*)&g_Pk[((long long)k * M_ + ri + 8) * B_ + cb] = v1;
        }
    }
}

// ---------------------------------------------------------------------------
// K4: accB = mean over k of Pk  (float4)
__global__ void acc_reduce() {
    int e = blockIdx.x * 256 + threadIdx.x;    // float4 index, 0..131071
    const float4* P = (const float4*)g_Pk;
    float4 s = P[e];
#pragma unroll
    for (int k = 1; k < K_; k++) {
        float4 t = P[k * (M_ * B_ / 4) + e];
        s.x += t.x; s.y += t.y; s.z += t.z; s.w += t.w;
    }
    const float inv = 1.f / (float)K_;
    s.x *= inv; s.y *= inv; s.z *= inv; s.w *= inv;
    ((float4*)g_acc)[e] = s;
}

// ---------------------------------------------------------------------------
// K5: S[i][j] = sqrt(acc[i][j%B]^2 + acc[j][i%B]^2 + f(dist(A_i,A_j))^2)
__global__ void __launch_bounds__(256, 2) s_mma() {
    __shared__ unsigned As[128 * SROW];
    __shared__ unsigned Bs[128 * SROW];

    int i0 = blockIdx.y * 128;
    int j0 = blockIdx.x * 128;
    int tid = threadIdx.x;
    int lane = tid & 31, warp = tid >> 5;
    int wm = warp >> 1, wn = warp & 1;
    int g = lane >> 2, t4 = lane & 3;

    MmaAcc acc;
    mma_tile_core(g_A + i0 * D_, g_A + j0 * D_, As, Bs, acc);

#pragma unroll
    for (int mt = 0; mt < 2; mt++) {
        int ri = i0 + wm * 32 + mt * 16 + g;
        float na0 = g_nA[ri];
        float na1 = g_nA[ri + 8];
        int im0 = ri & (B_ - 1);
        int im1 = (ri + 8) & (B_ - 1);
#pragma unroll
        for (int nt = 0; nt < 8; nt++) {
            int cj = j0 + wn * 64 + nt * 8 + 2 * t4;
            float nb0 = g_nA[cj];
            float nb1 = g_nA[cj + 1];
            float* cc = acc.c[mt][nt];
            float d00 = fdist(na0 + nb0 - 2.f * cc[0]);
            float d01 = fdist(na0 + nb1 - 2.f * cc[1]);
            float d10 = fdist(na1 + nb0 - 2.f * cc[2]);
            float d11 = fdist(na1 + nb1 - 2.f * cc[3]);
            int jm0 = cj & (B_ - 1);
            int jm1 = (cj + 1) & (B_ - 1);
            float a00 = g_acc[ri * B_ + jm0],       b00 = g_acc[cj * B_ + im0];
            float a01 = g_acc[ri * B_ + jm1],       b01 = g_acc[(cj + 1) * B_ + im0];
            float a10 = g_acc[(ri + 8) * B_ + jm0], b10 = g_acc[cj * B_ + im1];
            float a11 = g_acc[(ri + 8) * B_ + jm1], b11 = g_acc[(cj + 1) * B_ + im1];
            float2 v0, v1;
            v0.x = sqrtf(a00 * a00 + b00 * b00 + d00 * d00);
            v0.y = sqrtf(a01 * a01 + b01 * b01 + d01 * d01);
            v1.x = sqrtf(a10 * a10 + b10 * b10 + d10 * d10);
            v1.y = sqrtf(a11 * a11 + b11 * b11 + d11 * d11);
            *(float2*)&g_S[(long long)ri * M_ + cj] = v0;
            *(float2*)&g_S[(long long)(ri + 8) * M_ + cj] = v1;
        }
    }
}

// ---------------------------------------------------------------------------
// K6: per-row: max over all j, sumexp over j!=i, one positive at i^B side.
__global__ void __launch_bounds__(256) row_reduce() {
    int i = blockIdx.x;
    int tid = threadIdx.x;
    const float* row = g_S + (long long)i * M_;
    __shared__ float red[256];

    float mx = -1e30f;
    for (int j = tid; j < M_; j += 256) mx = fmaxf(mx, row[j]);
    red[tid] = mx;
    __syncthreads();
    for (int s = 128; s > 0; s >>= 1) {
        if (tid < s) red[tid] = fmaxf(red[tid], red[tid + s]);
        __syncthreads();
    }
    mx = red[0];
    __syncthreads();

    float sum = 0.f;
    for (int j = tid; j < M_; j += 256)
        if (j != i) sum += expf(row[j] - mx);
    red[tid] = sum;
    __syncthreads();
    for (int s = 128; s > 0; s >>= 1) {
        if (tid < s) red[tid] += red[tid + s];
        __syncthreads();
    }
    if (tid == 0) {
        int pos = (i < B_) ? (i + B_) : (i - B_);
        float log_prob = (row[pos] - mx) - logf(red[0]);
        g_loss[i] = -log_prob;    // TEMPERATURE/BASE_TEMPERATURE == 1
    }
}

// ---------------------------------------------------------------------------
// K7: final mean over M rows -> scalar
__global__ void __launch_bounds__(256) final_reduce(float* __restrict__ out) {
    int tid = threadIdx.x;
    __shared__ float red[256];
    float s = 0.f;
    for (int j = tid; j < M_; j += 256) s += g_loss[j];
    red[tid] = s;
    __syncthreads();
    for (int st = 128; st > 0; st >>= 1) {
        if (tid < st) red[tid] += red[tid + st];
        __syncthreads();
    }
    if (tid == 0) out[0] = red[0] * (1.f / (float)M_);
}

// ---------------------------------------------------------------------------
extern "C" void kernel_launch(void* const* d_in, const int* in_sizes, int n_in,
                              void* d_out, int out_size) {
    const float* features = (const float*)d_in[0];   // (512, 2, 128) f32
    const int*   indices  = (const int*)d_in[1];     // (512,) i32
    const float* saved    = (const float*)d_in[2];   // (100000, 128) f32
    const int*   rks      = (const int*)d_in[3];     // (100000, 50) i32
    float* out = (float*)d_out;

    build_anchor<<<M_, D_>>>(features);
    gather_neigh<<<K_ * B_, D_>>>(saved, indices, rks);
    pk_mma<<<dim3(B_ / 128, M_ / 128, K_), 256>>>();
    acc_reduce<<<(M_ * B_ / 4) / 256, 256>>>();
    s_mma<<<dim3(M_ / 128, M_ / 128), 256>>>();
    row_reduce<<<M_, 256>>>();
    final_reduce<<<1, 256>>>(out);
}

// round 3
// speedup vs baseline: 2.2121x; 1.5182x over previous
#include <cuda_runtime.h>
#include <math.h>

// Problem constants
#define B_   512
#define V_   2
#define D_   128
#define M_   1024          // V*B
#define K_   15            // TOP_K
#define KMAX 50
#define INV_T 14.285714285714286f   // 1/0.07
#define GRP  5             // k groups
#define KPG  3             // k per group

// Scratch (static device globals)
__device__ unsigned g_Abf[M_ * 64];        // anchors packed bf16x2 [i][d/2]
__device__ unsigned g_Gbf[K_ * B_ * 64];   // neighbors packed bf16x2
__device__ float g_nA[M_];                 // ||A_i||^2 (fp32 exact)
__device__ float g_nG[K_ * B_];            // ||G_r||^2
__device__ float g_accp[GRP * M_ * B_];    // per-group partial sums of f
__device__ float g_acc[M_ * B_];           // accB
__device__ float g_S[M_ * M_];             // logits_src
__device__ float g_loss[M_];               // per-row loss

// ---------------------------------------------------------------------------
__device__ __forceinline__ unsigned pack_bf(float lo, float hi) {
    unsigned r;
    asm("cvt.rn.bf16x2.f32 %0, %1, %2;" : "=r"(r) : "f"(hi), "f"(lo));
    return r;
}
__device__ __forceinline__ float rsq_ap(float x) {
    float r; asm("rsqrt.approx.f32 %0, %1;" : "=f"(r) : "f"(x)); return r;
}
__device__ __forceinline__ float rcp_ap(float x) {
    float r; asm("rcp.approx.f32 %0, %1;" : "=f"(r) : "f"(x)); return r;
}
__device__ __forceinline__ float fdist(float sq) {
    float d = (sq > 0.f) ? sq * rsq_ap(sq) : 0.f;   // sqrt(sq) via rsqrt
    return (1.f + rcp_ap(1.f + d)) * INV_T;
}
__device__ __forceinline__ void mma_bf16(float c[4], const unsigned a[4],
                                         unsigned b0, unsigned b1) {
    asm volatile(
        "mma.sync.aligned.m16n8k16.row.col.f32.bf16.bf16.f32 "
        "{%0,%1,%2,%3}, {%4,%5,%6,%7}, {%8,%9}, {%0,%1,%2,%3};\n"
        : "+f"(c[0]), "+f"(c[1]), "+f"(c[2]), "+f"(c[3])
        : "r"(a[0]), "r"(a[1]), "r"(a[2]), "r"(a[3]), "r"(b0), "r"(b1));
}

// ---------------------------------------------------------------------------
// K1: anchors -> bf16 pack + exact fp32 norms
__global__ void build_anchor(const float* __restrict__ features) {
    int i = blockIdx.x;
    int d = threadIdx.x;
    int v = i >> 9;
    int b = i & (B_ - 1);
    float val = features[(b * V_ + v) * D_ + d];

    __shared__ float sv[D_];
    __shared__ float red[D_];
    sv[d] = val;
    red[d] = val * val;
    __syncthreads();
    for (int s = D_ / 2; s > 0; s >>= 1) {
        if (d < s) red[d] += red[d + s];
        __syncthreads();
    }
    if (d == 0) g_nA[i] = red[0];
    if (d < 64) g_Abf[i * 64 + d] = pack_bf(sv[2 * d], sv[2 * d + 1]);
}

// K2: gather neighbors -> bf16 pack + norms
__global__ void gather_neigh(const float* __restrict__ saved,
                             const int* __restrict__ indices,
                             const int* __restrict__ rks) {
    int r = blockIdx.x;
    int d = threadIdx.x;
    int k = r / B_;
    int b = r - k * B_;
    int idx = rks[indices[b] * KMAX + k];
    float val = saved[(long long)idx * D_ + d];

    __shared__ float sv[D_];
    __shared__ float red[D_];
    sv[d] = val;
    red[d] = val * val;
    __syncthreads();
    for (int s = D_ / 2; s > 0; s >>= 1) {
        if (d < s) red[d] += red[d + s];
        __syncthreads();
    }
    if (d == 0) g_nG[r] = red[0];
    if (d < 64) g_Gbf[r * 64 + d] = pack_bf(sv[2 * d], sv[2 * d + 1]);
}

// ---------------------------------------------------------------------------
// K3: fused Pk+partial-acc. Tile 128(i) x 64(b), 256 thr = 8 warps (4m x 2n).
// Accumulates sum_k f(dist) over KPG k's in registers, writes one partial slab.
__global__ void __launch_bounds__(256, 2) pk_fused() {
    __shared__ unsigned As[128 * 64];   // full-D A tile, swizzled
    __shared__ unsigned Bs[64 * 32];    // half-D B chunk, swizzled

    int grp = blockIdx.z;
    int i0 = blockIdx.y * 128;
    int b0 = blockIdx.x * 64;
    int tid = threadIdx.x;
    int lane = tid & 31, warp = tid >> 5;
    int wm = warp >> 1, wn = warp & 1;
    int g = lane >> 2, t4 = lane & 3;

    // Fill A tile (once for all KPG k's)
#pragma unroll
    for (int q = 0; q < 8; q++) {
        int idx = q * 256 + tid;
        int row = idx >> 4, c4 = idx & 15;
        uint4 v = *(const uint4*)&g_Abf[(i0 + row) * 64 + c4 * 4];
        *(uint4*)&As[row * 64 + ((c4 * 4) ^ ((row & 7) << 2))] = v;
    }

    float fsum[2][4][4];
#pragma unroll
    for (int mt = 0; mt < 2; mt++)
#pragma unroll
        for (int nt = 0; nt < 4; nt++)
#pragma unroll
            for (int q = 0; q < 4; q++) fsum[mt][nt][q] = 0.f;

    for (int kk = 0; kk < KPG; kk++) {
        int k = grp * KPG + kk;
        const unsigned* Gb = g_Gbf + (k * B_ + b0) * 64;

        float dot[2][4][4];
#pragma unroll
        for (int mt = 0; mt < 2; mt++)
#pragma unroll
            for (int nt = 0; nt < 4; nt++)
#pragma unroll
                for (int q = 0; q < 4; q++) dot[mt][nt][q] = 0.f;

        for (int dc2 = 0; dc2 < 64; dc2 += 32) {
            __syncthreads();
#pragma unroll
            for (int q = 0; q < 2; q++) {
                int idx = q * 256 + tid;
                int row = idx >> 3, c4 = idx & 7;
                uint4 v = *(const uint4*)&Gb[row * 64 + dc2 + c4 * 4];
                *(uint4*)&Bs[row * 32 + ((c4 * 4) ^ ((row & 7) << 2))] = v;
            }
            __syncthreads();
#pragma unroll
            for (int s = 0; s < 4; s++) {
                int ca = dc2 + s * 8;
                unsigned a[2][4];
#pragma unroll
                for (int mt = 0; mt < 2; mt++) {
                    int r = wm * 32 + mt * 16 + g;
                    int sw = (r & 7) << 2;
                    a[mt][0] = As[r * 64 + ((ca + t4) ^ sw)];
                    a[mt][1] = As[(r + 8) * 64 + ((ca + t4) ^ sw)];
                    a[mt][2] = As[r * 64 + ((ca + 4 + t4) ^ sw)];
                    a[mt][3] = As[(r + 8) * 64 + ((ca + 4 + t4) ^ sw)];
                }
                int cb = s * 8;
#pragma unroll
                for (int nt = 0; nt < 4; nt++) {
                    int col = wn * 32 + nt * 8 + g;
                    int swb = (col & 7) << 2;
                    unsigned b0r = Bs[col * 32 + ((cb + t4) ^ swb)];
                    unsigned b1r = Bs[col * 32 + ((cb + 4 + t4) ^ swb)];
                    mma_bf16(dot[0][nt], a[0], b0r, b1r);
                    mma_bf16(dot[1][nt], a[1], b0r, b1r);
                }
            }
        }
        // epilogue for this k: accumulate f(dist)
#pragma unroll
        for (int mt = 0; mt < 2; mt++) {
            int ri = i0 + wm * 32 + mt * 16 + g;
            float na0 = g_nA[ri];
            float na1 = g_nA[ri + 8];
#pragma unroll
            for (int nt = 0; nt < 4; nt++) {
                int cb = b0 + wn * 32 + nt * 8 + 2 * t4;
                float ng0 = g_nG[k * B_ + cb];
                float ng1 = g_nG[k * B_ + cb + 1];
                float* dd = dot[mt][nt];
                fsum[mt][nt][0] += fdist(fmaxf(na0 + ng0 - 2.f * dd[0], 0.f));
                fsum[mt][nt][1] += fdist(fmaxf(na0 + ng1 - 2.f * dd[1], 0.f));
                fsum[mt][nt][2] += fdist(fmaxf(na1 + ng0 - 2.f * dd[2], 0.f));
                fsum[mt][nt][3] += fdist(fmaxf(na1 + ng1 - 2.f * dd[3], 0.f));
            }
        }
    }

    // write partial slab
    float* P = g_accp + (long long)grp * (M_ * B_);
#pragma unroll
    for (int mt = 0; mt < 2; mt++) {
        int ri = i0 + wm * 32 + mt * 16 + g;
#pragma unroll
        for (int nt = 0; nt < 4; nt++) {
            int cb = b0 + wn * 32 + nt * 8 + 2 * t4;
            *(float2*)&P[ri * B_ + cb] = make_float2(fsum[mt][nt][0], fsum[mt][nt][1]);
            *(float2*)&P[(ri + 8) * B_ + cb] = make_float2(fsum[mt][nt][2], fsum[mt][nt][3]);
        }
    }
}

// ---------------------------------------------------------------------------
// K4: accB = (sum over groups) / 15
__global__ void acc_reduce() {
    int e = blockIdx.x * 256 + threadIdx.x;       // float4 index
    const float4* P = (const float4*)g_accp;
    float4 s = P[e];
#pragma unroll
    for (int gp = 1; gp < GRP; gp++) {
        float4 t = P[gp * (M_ * B_ / 4) + e];
        s.x += t.x; s.y += t.y; s.z += t.z; s.w += t.w;
    }
    const float inv = 1.f / (float)K_;
    s.x *= inv; s.y *= inv; s.z *= inv; s.w *= inv;
    ((float4*)g_acc)[e] = s;
}

// ---------------------------------------------------------------------------
// K5: S[i][j] = sqrt(acc[i][j%B]^2 + acc[j][i%B]^2 + f(dist(A_i,A_j))^2)
// Same 128x64 bf16 core, B-tile rows come from g_Abf.
__global__ void __launch_bounds__(256, 2) s_fused() {
    __shared__ unsigned As[128 * 64];
    __shared__ unsigned Bs[64 * 32];

    int i0 = blockIdx.y * 128;
    int j0 = blockIdx.x * 64;
    int tid = threadIdx.x;
    int lane = tid & 31, warp = tid >> 5;
    int wm = warp >> 1, wn = warp & 1;
    int g = lane >> 2, t4 = lane & 3;

#pragma unroll
    for (int q = 0; q < 8; q++) {
        int idx = q * 256 + tid;
        int row = idx >> 4, c4 = idx & 15;
        uint4 v = *(const uint4*)&g_Abf[(i0 + row) * 64 + c4 * 4];
        *(uint4*)&As[row * 64 + ((c4 * 4) ^ ((row & 7) << 2))] = v;
    }

    float dot[2][4][4];
#pragma unroll
    for (int mt = 0; mt < 2; mt++)
#pragma unroll
        for (int nt = 0; nt < 4; nt++)
#pragma unroll
            for (int q = 0; q < 4; q++) dot[mt][nt][q] = 0.f;

    for (int dc2 = 0; dc2 < 64; dc2 += 32) {
        __syncthreads();
#pragma unroll
        for (int q = 0; q < 2; q++) {
            int idx = q * 256 + tid;
            int row = idx >> 3, c4 = idx & 7;
            uint4 v = *(const uint4*)&g_Abf[(j0 + row) * 64 + dc2 + c4 * 4];
            *(uint4*)&Bs[row * 32 + ((c4 * 4) ^ ((row & 7) << 2))] = v;
        }
        __syncthreads();
#pragma unroll
        for (int s = 0; s < 4; s++) {
            int ca = dc2 + s * 8;
            unsigned a[2][4];
#pragma unroll
            for (int mt = 0; mt < 2; mt++) {
                int r = wm * 32 + mt * 16 + g;
                int sw = (r & 7) << 2;
                a[mt][0] = As[r * 64 + ((ca + t4) ^ sw)];
                a[mt][1] = As[(r + 8) * 64 + ((ca + t4) ^ sw)];
                a[mt][2] = As[r * 64 + ((ca + 4 + t4) ^ sw)];
                a[mt][3] = As[(r + 8) * 64 + ((ca + 4 + t4) ^ sw)];
            }
            int cb = s * 8;
#pragma unroll
            for (int nt = 0; nt < 4; nt++) {
                int col = wn * 32 + nt * 8 + g;
                int swb = (col & 7) << 2;
                unsigned b0r = Bs[col * 32 + ((cb + t4) ^ swb)];
                unsigned b1r = Bs[col * 32 + ((cb + 4 + t4) ^ swb)];
                mma_bf16(dot[0][nt], a[0], b0r, b1r);
                mma_bf16(dot[1][nt], a[1], b0r, b1r);
            }
        }
    }

#pragma unroll
    for (int mt = 0; mt < 2; mt++) {
        int ri = i0 + wm * 32 + mt * 16 + g;
        float na0 = g_nA[ri];
        float na1 = g_nA[ri + 8];
        int im0 = ri & (B_ - 1);
        int im1 = (ri + 8) & (B_ - 1);
#pragma unroll
        for (int nt = 0; nt < 4; nt++) {
            int cj = j0 + wn * 32 + nt * 8 + 2 * t4;
            float nb0 = g_nA[cj];
            float nb1 = g_nA[cj + 1];
            float* dd = dot[mt][nt];
            float d00 = fdist(fmaxf(na0 + nb0 - 2.f * dd[0], 0.f));
            float d01 = fdist(fmaxf(na0 + nb1 - 2.f * dd[1], 0.f));
            float d10 = fdist(fmaxf(na1 + nb0 - 2.f * dd[2], 0.f));
            float d11 = fdist(fmaxf(na1 + nb1 - 2.f * dd[3], 0.f));
            int jm0 = cj & (B_ - 1);
            int jm1 = (cj + 1) & (B_ - 1);
            float a00 = g_acc[ri * B_ + jm0],       b00 = g_acc[cj * B_ + im0];
            float a01 = g_acc[ri * B_ + jm1],       b01 = g_acc[(cj + 1) * B_ + im0];
            float a10 = g_acc[(ri + 8) * B_ + jm0], b10 = g_acc[cj * B_ + im1];
            float a11 = g_acc[(ri + 8) * B_ + jm1], b11 = g_acc[(cj + 1) * B_ + im1];
            float2 v0, v1;
            v0.x = sqrtf(a00 * a00 + b00 * b00 + d00 * d00);
            v0.y = sqrtf(a01 * a01 + b01 * b01 + d01 * d01);
            v1.x = sqrtf(a10 * a10 + b10 * b10 + d10 * d10);
            v1.y = sqrtf(a11 * a11 + b11 * b11 + d11 * d11);
            *(float2*)&g_S[(long long)ri * M_ + cj] = v0;
            *(float2*)&g_S[(long long)(ri + 8) * M_ + cj] = v1;
        }
    }
}

// ---------------------------------------------------------------------------
// K6: per-row softmax-style reduction
__global__ void __launch_bounds__(256) row_reduce() {
    int i = blockIdx.x;
    int tid = threadIdx.x;
    const float* row = g_S + (long long)i * M_;
    __shared__ float red[256];

    float mx = -1e30f;
    for (int j = tid; j < M_; j += 256) mx = fmaxf(mx, row[j]);
    red[tid] = mx;
    __syncthreads();
    for (int s = 128; s > 0; s >>= 1) {
        if (tid < s) red[tid] = fmaxf(red[tid], red[tid + s]);
        __syncthreads();
    }
    mx = red[0];
    __syncthreads();

    float sum = 0.f;
    for (int j = tid; j < M_; j += 256)
        if (j != i) sum += expf(row[j] - mx);
    red[tid] = sum;
    __syncthreads();
    for (int s = 128; s > 0; s >>= 1) {
        if (tid < s) red[tid] += red[tid + s];
        __syncthreads();
    }
    if (tid == 0) {
        int pos = (i < B_) ? (i + B_) : (i - B_);
        float log_prob = (row[pos] - mx) - logf(red[0]);
        g_loss[i] = -log_prob;
    }
}

// K7: final mean
__global__ void __launch_bounds__(256) final_reduce(float* __restrict__ out) {
    int tid = threadIdx.x;
    __shared__ float red[256];
    float s = 0.f;
    for (int j = tid; j < M_; j += 256) s += g_loss[j];
    red[tid] = s;
    __syncthreads();
    for (int st = 128; st > 0; st >>= 1) {
        if (tid < st) red[tid] += red[tid + st];
        __syncthreads();
    }
    if (tid == 0) out[0] = red[0] * (1.f / (float)M_);
}

// ---------------------------------------------------------------------------
extern "C" void kernel_launch(void* const* d_in, const int* in_sizes, int n_in,
                              void* d_out, int out_size) {
    const float* features = (const float*)d_in[0];   // (512, 2, 128) f32
    const int*   indices  = (const int*)d_in[1];     // (512,) i32
    const float* saved    = (const float*)d_in[2];   // (100000, 128) f32
    const int*   rks      = (const int*)d_in[3];     // (100000, 50) i32
    float* out = (float*)d_out;

    build_anchor<<<M_, D_>>>(features);
    gather_neigh<<<K_ * B_, D_>>>(saved, indices, rks);
    pk_fused<<<dim3(B_ / 64, M_ / 128, GRP), 256>>>();
    acc_reduce<<<(M_ * B_ / 4) / 256, 256>>>();
    s_fused<<<dim3(M_ / 64, M_ / 128), 256>>>();
    row_reduce<<<M_, 256>>>();
    final_reduce<<<1, 256>>>(out);
}

// round 6
// speedup vs baseline: 2.3458x; 1.0604x over previous
#include <cuda_runtime.h>
#include <math.h>

// Problem constants
#define B_   512
#define V_   2
#define D_   128
#define M_   1024          // V*B
#define K_   15            // TOP_K
#define KMAX 50
#define INV_T 14.285714285714286f   // 1/0.07

// Scratch (static device globals)
__device__ unsigned g_Abf[M_ * 64];        // anchors packed bf16x2 [i][d/2]
__device__ unsigned g_Gbf[K_ * B_ * 64];   // neighbors packed bf16x2
__device__ float g_nA[M_];                 // ||A_i||^2 (fp32 exact)
__device__ float g_nG[K_ * B_];            // ||G_r||^2
__device__ float g_acc[M_ * B_];           // accB
__device__ float g_S[M_ * M_];             // logits_src
__device__ int   g_rmax[M_];               // per-row max (float bits, >0)
__device__ float g_loss[M_];               // per-row loss

// ---------------------------------------------------------------------------
__device__ __forceinline__ unsigned pack_bf(float lo, float hi) {
    unsigned r;
    asm("cvt.rn.bf16x2.f32 %0, %1, %2;" : "=r"(r) : "f"(hi), "f"(lo));
    return r;
}
__device__ __forceinline__ float rsq_ap(float x) {
    float r; asm("rsqrt.approx.f32 %0, %1;" : "=f"(r) : "f"(x)); return r;
}
__device__ __forceinline__ float rcp_ap(float x) {
    float r; asm("rcp.approx.f32 %0, %1;" : "=f"(r) : "f"(x)); return r;
}
__device__ __forceinline__ float fdist(float sq) {
    float d = (sq > 0.f) ? sq * rsq_ap(sq) : 0.f;   // sqrt(sq) via rsqrt
    return (1.f + rcp_ap(1.f + d)) * INV_T;
}
__device__ __forceinline__ void mma_bf16(float c[4], const unsigned a[4],
                                         unsigned b0, unsigned b1) {
    asm volatile(
        "mma.sync.aligned.m16n8k16.row.col.f32.bf16.bf16.f32 "
        "{%0,%1,%2,%3}, {%4,%5,%6,%7}, {%8,%9}, {%0,%1,%2,%3};\n"
        : "+f"(c[0]), "+f"(c[1]), "+f"(c[2]), "+f"(c[3])
        : "r"(a[0]), "r"(a[1]), "r"(a[2]), "r"(a[3]), "r"(b0), "r"(b1));
}

// ---------------------------------------------------------------------------
// K1: anchors -> bf16 pack + exact fp32 norms; also reset g_rmax (per replay)
__global__ void build_anchor(const float* __restrict__ features) {
    int i = blockIdx.x;
    int d = threadIdx.x;
    int v = i >> 9;
    int b = i & (B_ - 1);
    float val = features[(b * V_ + v) * D_ + d];

    __shared__ float sv[D_];
    __shared__ float red[D_];
    sv[d] = val;
    red[d] = val * val;
    __syncthreads();
    for (int s = D_ / 2; s > 0; s >>= 1) {
        if (d < s) red[d] += red[d + s];
        __syncthreads();
    }
    if (d == 0) { g_nA[i] = red[0]; g_rmax[i] = 0; }
    if (d < 64) g_Abf[i * 64 + d] = pack_bf(sv[2 * d], sv[2 * d + 1]);
}

// K2: gather neighbors -> bf16 pack + norms
__global__ void gather_neigh(const float* __restrict__ saved,
                             const int* __restrict__ indices,
                             const int* __restrict__ rks) {
    int r = blockIdx.x;
    int d = threadIdx.x;
    int k = r / B_;
    int b = r - k * B_;
    int idx = rks[indices[b] * KMAX + k];
    float val = saved[(long long)idx * D_ + d];

    __shared__ float sv[D_];
    __shared__ float red[D_];
    sv[d] = val;
    red[d] = val * val;
    __syncthreads();
    for (int s = D_ / 2; s > 0; s >>= 1) {
        if (d < s) red[d] += red[d + s];
        __syncthreads();
    }
    if (d == 0) g_nG[r] = red[0];
    if (d < 64) g_Gbf[r * 64 + d] = pack_bf(sv[2 * d], sv[2 * d + 1]);
}

// ---------------------------------------------------------------------------
// K3: accB directly. Tile 64(i) x 64(b), 256 thr = 8 warps (4m x 2n),
// warp tile 16x32. Accumulates all 15 k's in registers, writes g_acc once.
__global__ void __launch_bounds__(256, 2) pk_all() {
    __shared__ unsigned As[64 * 64];
    __shared__ unsigned Bs[64 * 64];

    int i0 = blockIdx.y * 64;
    int b0 = blockIdx.x * 64;
    int tid = threadIdx.x;
    int lane = tid & 31, warp = tid >> 5;
    int wm = warp >> 1, wn = warp & 1;
    int g = lane >> 2, t4 = lane & 3;

    // Fill A tile once (full D)
#pragma unroll
    for (int q = 0; q < 4; q++) {
        int idx = q * 256 + tid;
        int row = idx >> 4, c4 = idx & 15;
        uint4 v = *(const uint4*)&g_Abf[(i0 + row) * 64 + c4 * 4];
        *(uint4*)&As[row * 64 + ((c4 * 4) ^ ((row & 7) << 2))] = v;
    }

    float fsum[4][4];
#pragma unroll
    for (int nt = 0; nt < 4; nt++)
#pragma unroll
        for (int q = 0; q < 4; q++) fsum[nt][q] = 0.f;

    int r = wm * 16 + g;
    int sw = (g & 7) << 2;           // (r&7)==(g&7)

#pragma unroll 1
    for (int k = 0; k < K_; k++) {
        __syncthreads();
        const unsigned* Gb = g_Gbf + (k * B_ + b0) * 64;
#pragma unroll
        for (int q = 0; q < 4; q++) {
            int idx = q * 256 + tid;
            int row = idx >> 4, c4 = idx & 15;
            uint4 v = *(const uint4*)&Gb[row * 64 + c4 * 4];
            *(uint4*)&Bs[row * 64 + ((c4 * 4) ^ ((row & 7) << 2))] = v;
        }
        __syncthreads();

        float dot[4][4];
#pragma unroll
        for (int nt = 0; nt < 4; nt++)
#pragma unroll
            for (int q = 0; q < 4; q++) dot[nt][q] = 0.f;

#pragma unroll
        for (int s = 0; s < 8; s++) {
            int ca = s * 8;
            unsigned a[4];
            a[0] = As[r * 64 + ((ca + t4) ^ sw)];
            a[1] = As[(r + 8) * 64 + ((ca + t4) ^ sw)];
            a[2] = As[r * 64 + ((ca + 4 + t4) ^ sw)];
            a[3] = As[(r + 8) * 64 + ((ca + 4 + t4) ^ sw)];
#pragma unroll
            for (int nt = 0; nt < 4; nt++) {
                int col = wn * 32 + nt * 8 + g;
                int swb = (col & 7) << 2;
                unsigned b0r = Bs[col * 64 + ((ca + t4) ^ swb)];
                unsigned b1r = Bs[col * 64 + ((ca + 4 + t4) ^ swb)];
                mma_bf16(dot[nt], a, b0r, b1r);
            }
        }
        // fold f(dist) for this k
        int ri = i0 + r;
        float na0 = g_nA[ri];
        float na1 = g_nA[ri + 8];
#pragma unroll
        for (int nt = 0; nt < 4; nt++) {
            int cb = b0 + wn * 32 + nt * 8 + 2 * t4;
            float ng0 = g_nG[k * B_ + cb];
            float ng1 = g_nG[k * B_ + cb + 1];
            float* dd = dot[nt];
            fsum[nt][0] += fdist(fmaxf(na0 + ng0 - 2.f * dd[0], 0.f));
            fsum[nt][1] += fdist(fmaxf(na0 + ng1 - 2.f * dd[1], 0.f));
            fsum[nt][2] += fdist(fmaxf(na1 + ng0 - 2.f * dd[2], 0.f));
            fsum[nt][3] += fdist(fmaxf(na1 + ng1 - 2.f * dd[3], 0.f));
        }
    }

    const float inv = 1.f / (float)K_;
    int ri = i0 + r;
#pragma unroll
    for (int nt = 0; nt < 4; nt++) {
        int cb = b0 + wn * 32 + nt * 8 + 2 * t4;
        *(float2*)&g_acc[ri * B_ + cb] =
            make_float2(fsum[nt][0] * inv, fsum[nt][1] * inv);
        *(float2*)&g_acc[(ri + 8) * B_ + cb] =
            make_float2(fsum[nt][2] * inv, fsum[nt][3] * inv);
    }
}

// ---------------------------------------------------------------------------
// K5: S[i][j] = sqrt(acc[i][j%B]^2 + acc[j][i%B]^2 + f(dist)^2); also row max.
// Tile 128(i) x 64(j), 256 thr = 8 warps (4m x 2n), warp tile 32x32.
__global__ void __launch_bounds__(256, 2) s_fused() {
    __shared__ unsigned As[128 * 64];
    __shared__ unsigned Bs[64 * 32];
    __shared__ int srmax[128];

    int i0 = blockIdx.y * 128;
    int j0 = blockIdx.x * 64;
    int tid = threadIdx.x;
    int lane = tid & 31, warp = tid >> 5;
    int wm = warp >> 1, wn = warp & 1;
    int g = lane >> 2, t4 = lane & 3;

#pragma unroll
    for (int q = 0; q < 8; q++) {
        int idx = q * 256 + tid;
        int row = idx >> 4, c4 = idx & 15;
        uint4 v = *(const uint4*)&g_Abf[(i0 + row) * 64 + c4 * 4];
        *(uint4*)&As[row * 64 + ((c4 * 4) ^ ((row & 7) << 2))] = v;
    }
    if (tid < 128) srmax[tid] = 0;

    float dot[2][4][4];
#pragma unroll
    for (int mt = 0; mt < 2; mt++)
#pragma unroll
        for (int nt = 0; nt < 4; nt++)
#pragma unroll
            for (int q = 0; q < 4; q++) dot[mt][nt][q] = 0.f;

#pragma unroll 1
    for (int dc2 = 0; dc2 < 64; dc2 += 32) {
        __syncthreads();
#pragma unroll
        for (int q = 0; q < 2; q++) {
            int idx = q * 256 + tid;
            int row = idx >> 3, c4 = idx & 7;
            uint4 v = *(const uint4*)&g_Abf[(j0 + row) * 64 + dc2 + c4 * 4];
            *(uint4*)&Bs[row * 32 + ((c4 * 4) ^ ((row & 7) << 2))] = v;
        }
        __syncthreads();
#pragma unroll
        for (int s = 0; s < 4; s++) {
            int ca = dc2 + s * 8;
            unsigned a[2][4];
#pragma unroll
            for (int mt = 0; mt < 2; mt++) {
                int rr = wm * 32 + mt * 16 + g;
                int sw = (rr & 7) << 2;
                a[mt][0] = As[rr * 64 + ((ca + t4) ^ sw)];
                a[mt][1] = As[(rr + 8) * 64 + ((ca + t4) ^ sw)];
                a[mt][2] = As[rr * 64 + ((ca + 4 + t4) ^ sw)];
                a[mt][3] = As[(rr + 8) * 64 + ((ca + 4 + t4) ^ sw)];
            }
            int cb = s * 8;
#pragma unroll
            for (int nt = 0; nt < 4; nt++) {
                int col = wn * 32 + nt * 8 + g;
                int swb = (col & 7) << 2;
                unsigned b0r = Bs[col * 32 + ((cb + t4) ^ swb)];
                unsigned b1r = Bs[col * 32 + ((cb + 4 + t4) ^ swb)];
                mma_bf16(dot[0][nt], a[0], b0r, b1r);
                mma_bf16(dot[1][nt], a[1], b0r, b1r);
            }
        }
    }

#pragma unroll
    for (int mt = 0; mt < 2; mt++) {
        int ri = i0 + wm * 32 + mt * 16 + g;
        float na0 = g_nA[ri];
        float na1 = g_nA[ri + 8];
        int im0 = ri & (B_ - 1);
        int im1 = (ri + 8) & (B_ - 1);
        float m0 = 0.f, m1 = 0.f;
#pragma unroll
        for (int nt = 0; nt < 4; nt++) {
            int cj = j0 + wn * 32 + nt * 8 + 2 * t4;
            float nb0 = g_nA[cj];
            float nb1 = g_nA[cj + 1];
            float* dd = dot[mt][nt];
            float d00 = fdist(fmaxf(na0 + nb0 - 2.f * dd[0], 0.f));
            float d01 = fdist(fmaxf(na0 + nb1 - 2.f * dd[1], 0.f));
            float d10 = fdist(fmaxf(na1 + nb0 - 2.f * dd[2], 0.f));
            float d11 = fdist(fmaxf(na1 + nb1 - 2.f * dd[3], 0.f));
            int jm0 = cj & (B_ - 1);
            int jm1 = (cj + 1) & (B_ - 1);
            float a00 = g_acc[ri * B_ + jm0],       b00 = g_acc[cj * B_ + im0];
            float a01 = g_acc[ri * B_ + jm1],       b01 = g_acc[(cj + 1) * B_ + im0];
            float a10 = g_acc[(ri + 8) * B_ + jm0], b10 = g_acc[cj * B_ + im1];
            float a11 = g_acc[(ri + 8) * B_ + jm1], b11 = g_acc[(cj + 1) * B_ + im1];
            float2 v0, v1;
            v0.x = sqrtf(a00 * a00 + b00 * b00 + d00 * d00);
            v0.y = sqrtf(a01 * a01 + b01 * b01 + d01 * d01);
            v1.x = sqrtf(a10 * a10 + b10 * b10 + d10 * d10);
            v1.y = sqrtf(a11 * a11 + b11 * b11 + d11 * d11);
            *(float2*)&g_S[(long long)ri * M_ + cj] = v0;
            *(float2*)&g_S[(long long)(ri + 8) * M_ + cj] = v1;
            m0 = fmaxf(m0, fmaxf(v0.x, v0.y));
            m1 = fmaxf(m1, fmaxf(v1.x, v1.y));
        }
        // fold over t4 quad (exact max -> deterministic)
        m0 = fmaxf(m0, __shfl_xor_sync(0xffffffffu, m0, 1));
        m0 = fmaxf(m0, __shfl_xor_sync(0xffffffffu, m0, 2));
        m1 = fmaxf(m1, __shfl_xor_sync(0xffffffffu, m1, 1));
        m1 = fmaxf(m1, __shfl_xor_sync(0xffffffffu, m1, 2));
        if (t4 == 0) {
            atomicMax(&srmax[wm * 32 + mt * 16 + g], __float_as_int(m0));
            atomicMax(&srmax[wm * 32 + mt * 16 + 8 + g], __float_as_int(m1));
        }
    }
    __syncthreads();
    if (tid < 128) atomicMax(&g_rmax[i0 + tid], srmax[tid]);
}

// ---------------------------------------------------------------------------
// K6: per-row single pass: sumexp over j!=i with precomputed max; pos lookup.
__global__ void __launch_bounds__(256) row_sum() {
    int i = blockIdx.x;
    int tid = threadIdx.x;
    __shared__ float red[256];
    __shared__ float spos;

    float mx = __int_as_float(g_rmax[i]);
    int pos = (i < B_) ? (i + B_) : (i - B_);

    const float4* row4 = (const float4*)(g_S + (long long)i * M_);
    float4 v = row4[tid];
    if (tid == (pos >> 2)) spos = ((const float*)&v)[pos & 3];

    int jb = tid * 4;
    float s = 0.f;
    s += (jb + 0 != i) ? __expf(v.x - mx) : 0.f;
    s += (jb + 1 != i) ? __expf(v.y - mx) : 0.f;
    s += (jb + 2 != i) ? __expf(v.z - mx) : 0.f;
    s += (jb + 3 != i) ? __expf(v.w - mx) : 0.f;

    red[tid] = s;
    __syncthreads();   // orders spos write before the tid==0 read below
    for (int st = 128; st > 0; st >>= 1) {
        if (tid < st) red[tid] += red[tid + st];
        __syncthreads();
    }
    if (tid == 0) {
        float log_prob = (spos - mx) - logf(red[0]);
        g_loss[i] = -log_prob;
    }
}

// K7: final mean
__global__ void __launch_bounds__(256) final_reduce(float* __restrict__ out) {
    int tid = threadIdx.x;
    __shared__ float red[256];
    float s = 0.f;
    for (int j = tid; j < M_; j += 256) s += g_loss[j];
    red[tid] = s;
    __syncthreads();
    for (int st = 128; st > 0; st >>= 1) {
        if (tid < st) red[tid] += red[tid + st];
        __syncthreads();
    }
    if (tid == 0) out[0] = red[0] * (1.f / (float)M_);
}

// ---------------------------------------------------------------------------
extern "C" void kernel_launch(void* const* d_in, const int* in_sizes, int n_in,
                              void* d_out, int out_size) {
    const float* features = (const float*)d_in[0];   // (512, 2, 128) f32
    const int*   indices  = (const int*)d_in[1];     // (512,) i32
    const float* saved    = (const float*)d_in[2];   // (100000, 128) f32
    const int*   rks      = (const int*)d_in[3];     // (100000, 50) i32
    float* out = (float*)d_out;

    build_anchor<<<M_, D_>>>(features);
    gather_neigh<<<K_ * B_, D_>>>(saved, indices, rks);
    pk_all<<<dim3(B_ / 64, M_ / 64), 256>>>();
    s_fused<<<dim3(M_ / 64, M_ / 128), 256>>>();
    row_sum<<<M_, 256>>>();
    final_reduce<<<1, 256>>>(out);
}

// round 8
// speedup vs baseline: 2.7117x; 1.1560x over previous
#include <cuda_runtime.h>
#include <math.h>

// Problem constants
#define B_   512
#define V_   2
#define D_   128
#define M_   1024          // V*B
#define K_   15            // TOP_K
#define KMAX 50
#define INV_T 14.285714285714286f   // 1/0.07

// Scratch (static device globals)
__device__ unsigned g_Abf[M_ * 64];        // anchors packed bf16x2 [i][d/2]
__device__ unsigned g_Gbf[K_ * B_ * 64];   // neighbors packed bf16x2
__device__ float g_nA[M_];                 // ||A_i||^2 (fp32 exact)
__device__ float g_nG[K_ * B_];            // ||G_r||^2
__device__ float g_acc[M_ * B_];           // accB [i][b]
__device__ float g_accT[B_ * M_];          // accB transposed [b][i]
__device__ float g_S[M_ * M_];             // logits_src
__device__ int   g_rmax[M_];               // per-row max (float bits, >0)
__device__ float g_loss[M_];               // per-row loss

// ---------------------------------------------------------------------------
__device__ __forceinline__ unsigned pack_bf(float lo, float hi) {
    unsigned r;
    asm("cvt.rn.bf16x2.f32 %0, %1, %2;" : "=r"(r) : "f"(hi), "f"(lo));
    return r;
}
__device__ __forceinline__ float rsq_ap(float x) {
    float r; asm("rsqrt.approx.f32 %0, %1;" : "=f"(r) : "f"(x)); return r;
}
__device__ __forceinline__ float rcp_ap(float x) {
    float r; asm("rcp.approx.f32 %0, %1;" : "=f"(r) : "f"(x)); return r;
}
__device__ __forceinline__ float fdist(float sq) {
    float d = (sq > 0.f) ? sq * rsq_ap(sq) : 0.f;   // sqrt(sq) via rsqrt
    return (1.f + rcp_ap(1.f + d)) * INV_T;
}
__device__ __forceinline__ void mma_bf16(float c[4], const unsigned a[4],
                                         unsigned b0, unsigned b1) {
    asm volatile(
        "mma.sync.aligned.m16n8k16.row.col.f32.bf16.bf16.f32 "
        "{%0,%1,%2,%3}, {%4,%5,%6,%7}, {%8,%9}, {%0,%1,%2,%3};\n"
        : "+f"(c[0]), "+f"(c[1]), "+f"(c[2]), "+f"(c[3])
        : "r"(a[0]), "r"(a[1]), "r"(a[2]), "r"(a[3]), "r"(b0), "r"(b1));
}
__device__ __forceinline__ void ldsm_x4(unsigned r[4], unsigned addr) {
    asm volatile(
        "ldmatrix.sync.aligned.m8n8.x4.shared.b16 {%0,%1,%2,%3}, [%4];"
        : "=r"(r[0]), "=r"(r[1]), "=r"(r[2]), "=r"(r[3]) : "r"(addr));
}
__device__ __forceinline__ unsigned sm_u32(const void* p) {
    return (unsigned)__cvta_generic_to_shared(p);
}

// ---------------------------------------------------------------------------
// K1: anchors -> bf16 pack + exact fp32 norms; also reset g_rmax (per replay)
__global__ void build_anchor(const float* __restrict__ features) {
    int i = blockIdx.x;
    int d = threadIdx.x;
    int v = i >> 9;
    int b = i & (B_ - 1);
    float val = features[(b * V_ + v) * D_ + d];

    __shared__ float sv[D_];
    __shared__ float red[D_];
    sv[d] = val;
    red[d] = val * val;
    __syncthreads();
    for (int s = D_ / 2; s > 0; s >>= 1) {
        if (d < s) red[d] += red[d + s];
        __syncthreads();
    }
    if (d == 0) { g_nA[i] = red[0]; g_rmax[i] = 0; }
    if (d < 64) g_Abf[i * 64 + d] = pack_bf(sv[2 * d], sv[2 * d + 1]);
}

// K2: gather neighbors -> bf16 pack + norms
__global__ void gather_neigh(const float* __restrict__ saved,
                             const int* __restrict__ indices,
                             const int* __restrict__ rks) {
    int r = blockIdx.x;
    int d = threadIdx.x;
    int k = r / B_;
    int b = r - k * B_;
    int idx = rks[indices[b] * KMAX + k];
    float val = saved[(long long)idx * D_ + d];

    __shared__ float sv[D_];
    __shared__ float red[D_];
    sv[d] = val;
    red[d] = val * val;
    __syncthreads();
    for (int s = D_ / 2; s > 0; s >>= 1) {
        if (d < s) red[d] += red[d + s];
        __syncthreads();
    }
    if (d == 0) g_nG[r] = red[0];
    if (d < 64) g_Gbf[r * 64 + d] = pack_bf(sv[2 * d], sv[2 * d + 1]);
}

// ---------------------------------------------------------------------------
// K3: accB (and accB^T) directly. Tile 64(i) x 64(b), 256 thr = 8 warps
// (4m x 2n), warp tile 16x32. ldmatrix operand loads, double-buffered B tile.
__global__ void __launch_bounds__(256, 2) pk_all() {
    __shared__ unsigned As[64 * 64];
    __shared__ unsigned Bs[2][64 * 64];

    int i0 = blockIdx.y * 64;
    int b0 = blockIdx.x * 64;
    int tid = threadIdx.x;
    int lane = tid & 31, warp = tid >> 5;
    int wm = warp >> 1, wn = warp & 1;
    int g = lane >> 2, t4 = lane & 3;
    int l7 = lane & 7;

    // Fill A tile once (full D)
#pragma unroll
    for (int q = 0; q < 4; q++) {
        int idx = q * 256 + tid;
        int row = idx >> 4, c4 = idx & 15;
        uint4 v = *(const uint4*)&g_Abf[(i0 + row) * 64 + c4 * 4];
        *(uint4*)&As[row * 64 + ((c4 * 4) ^ ((row & 7) << 2))] = v;
    }

    // ldmatrix lane addressing (byte offsets; row stride 64 words = 256 B)
    unsigned swl = l7 << 2;
    unsigned aBase = sm_u32(As) + (wm * 16 + (lane & 15)) * 256;
    unsigned koA = (lane >> 4) << 2;
    unsigned bRow0 = wn * 32 + ((lane >> 4) & 1) * 8 + l7;       // p=0 pair
    unsigned koB = ((lane >> 3) & 1) << 2;
    unsigned bBase0 = sm_u32(Bs) + bRow0 * 256;                  // + p*16rows
    unsigned bBase1 = bBase0 + 16 * 256;

    float fsum[4][4];
#pragma unroll
    for (int nt = 0; nt < 4; nt++)
#pragma unroll
        for (int q = 0; q < 4; q++) fsum[nt][q] = 0.f;

    // prefetch k=0 B tile into registers
    uint4 pre[4];
    {
        const unsigned* Gb = g_Gbf + (0 * B_ + b0) * 64;
#pragma unroll
        for (int q = 0; q < 4; q++) {
            int idx = q * 256 + tid;
            int row = idx >> 4, c4 = idx & 15;
            pre[q] = *(const uint4*)&Gb[row * 64 + c4 * 4];
        }
    }

    int cur = 0;
#pragma unroll 1
    for (int k = 0; k < K_; k++) {
        // store prefetched tile
#pragma unroll
        for (int q = 0; q < 4; q++) {
            int idx = q * 256 + tid;
            int row = idx >> 4, c4 = idx & 15;
            *(uint4*)&Bs[cur][row * 64 + ((c4 * 4) ^ ((row & 7) << 2))] = pre[q];
        }
        __syncthreads();

        // prefetch next k
        if (k + 1 < K_) {
            const unsigned* Gb = g_Gbf + ((k + 1) * B_ + b0) * 64;
#pragma unroll
            for (int q = 0; q < 4; q++) {
                int idx = q * 256 + tid;
                int row = idx >> 4, c4 = idx & 15;
                pre[q] = *(const uint4*)&Gb[row * 64 + c4 * 4];
            }
        }

        float dot[4][4];
#pragma unroll
        for (int nt = 0; nt < 4; nt++)
#pragma unroll
            for (int q = 0; q < 4; q++) dot[nt][q] = 0.f;

        unsigned bcur = (unsigned)(cur * (64 * 64 * 4));
#pragma unroll
        for (int s = 0; s < 8; s++) {
            unsigned a[4], bb0[4], bb1[4];
            ldsm_x4(a, aBase + ((((unsigned)(s * 8) + koA) ^ swl) << 2));
            ldsm_x4(bb0, bBase0 + bcur + ((((unsigned)(s * 8) + koB) ^ swl) << 2));
            ldsm_x4(bb1, bBase1 + bcur + ((((unsigned)(s * 8) + koB) ^ swl) << 2));
            mma_bf16(dot[0], a, bb0[0], bb0[1]);
            mma_bf16(dot[1], a, bb0[2], bb0[3]);
            mma_bf16(dot[2], a, bb1[0], bb1[1]);
            mma_bf16(dot[3], a, bb1[2], bb1[3]);
        }

        // fold f(dist) for this k
        int ri = i0 + wm * 16 + g;
        float na0 = g_nA[ri];
        float na1 = g_nA[ri + 8];
#pragma unroll
        for (int nt = 0; nt < 4; nt++) {
            int cb = b0 + wn * 32 + nt * 8 + 2 * t4;
            float ng0 = g_nG[k * B_ + cb];
            float ng1 = g_nG[k * B_ + cb + 1];
            float* dd = dot[nt];
            fsum[nt][0] += fdist(fmaxf(na0 + ng0 - 2.f * dd[0], 0.f));
            fsum[nt][1] += fdist(fmaxf(na0 + ng1 - 2.f * dd[1], 0.f));
            fsum[nt][2] += fdist(fmaxf(na1 + ng0 - 2.f * dd[2], 0.f));
            fsum[nt][3] += fdist(fmaxf(na1 + ng1 - 2.f * dd[3], 0.f));
        }
        cur ^= 1;
    }

    const float inv = 1.f / (float)K_;
    int ri = i0 + wm * 16 + g;
#pragma unroll
    for (int nt = 0; nt < 4; nt++) {
        int cb = b0 + wn * 32 + nt * 8 + 2 * t4;
        float v00 = fsum[nt][0] * inv, v01 = fsum[nt][1] * inv;
        float v10 = fsum[nt][2] * inv, v11 = fsum[nt][3] * inv;
        *(float2*)&g_acc[ri * B_ + cb] = make_float2(v00, v01);
        *(float2*)&g_acc[(ri + 8) * B_ + cb] = make_float2(v10, v11);
        g_accT[cb * M_ + ri] = v00;
        g_accT[(cb + 1) * M_ + ri] = v01;
        g_accT[cb * M_ + ri + 8] = v10;
        g_accT[(cb + 1) * M_ + ri + 8] = v11;
    }
}

// ---------------------------------------------------------------------------
// K5: S[i][j] = sqrt(acc[i][j%B]^2 + acc[j][i%B]^2 + f(dist)^2); plus row max.
// Tile 64(i) x 64(j), 256 thr = 8 warps (4m x 2n), warp tile 16x32, ldmatrix.
__global__ void __launch_bounds__(256, 2) s_fused() {
    __shared__ unsigned As[64 * 64];
    __shared__ unsigned Bs[64 * 64];
    __shared__ int srmax[64];

    int i0 = blockIdx.y * 64;
    int j0 = blockIdx.x * 64;
    int tid = threadIdx.x;
    int lane = tid & 31, warp = tid >> 5;
    int wm = warp >> 1, wn = warp & 1;
    int g = lane >> 2, t4 = lane & 3;
    int l7 = lane & 7;

#pragma unroll
    for (int q = 0; q < 4; q++) {
        int idx = q * 256 + tid;
        int row = idx >> 4, c4 = idx & 15;
        uint4 va = *(const uint4*)&g_Abf[(i0 + row) * 64 + c4 * 4];
        *(uint4*)&As[row * 64 + ((c4 * 4) ^ ((row & 7) << 2))] = va;
        uint4 vb = *(const uint4*)&g_Abf[(j0 + row) * 64 + c4 * 4];
        *(uint4*)&Bs[row * 64 + ((c4 * 4) ^ ((row & 7) << 2))] = vb;
    }
    if (tid < 64) srmax[tid] = 0;
    __syncthreads();

    unsigned swl = l7 << 2;
    unsigned aBase = sm_u32(As) + (wm * 16 + (lane & 15)) * 256;
    unsigned koA = (lane >> 4) << 2;
    unsigned bRow0 = wn * 32 + ((lane >> 4) & 1) * 8 + l7;
    unsigned koB = ((lane >> 3) & 1) << 2;
    unsigned bBase0 = sm_u32(Bs) + bRow0 * 256;
    unsigned bBase1 = bBase0 + 16 * 256;

    float dot[4][4];
#pragma unroll
    for (int nt = 0; nt < 4; nt++)
#pragma unroll
        for (int q = 0; q < 4; q++) dot[nt][q] = 0.f;

#pragma unroll
    for (int s = 0; s < 8; s++) {
        unsigned a[4], bb0[4], bb1[4];
        ldsm_x4(a, aBase + ((((unsigned)(s * 8) + koA) ^ swl) << 2));
        ldsm_x4(bb0, bBase0 + ((((unsigned)(s * 8) + koB) ^ swl) << 2));
        ldsm_x4(bb1, bBase1 + ((((unsigned)(s * 8) + koB) ^ swl) << 2));
        mma_bf16(dot[0], a, bb0[0], bb0[1]);
        mma_bf16(dot[1], a, bb0[2], bb0[3]);
        mma_bf16(dot[2], a, bb1[0], bb1[1]);
        mma_bf16(dot[3], a, bb1[2], bb1[3]);
    }

    int ri = i0 + wm * 16 + g;
    float na0 = g_nA[ri];
    float na1 = g_nA[ri + 8];
    int im0 = ri & (B_ - 1);
    int im1 = (ri + 8) & (B_ - 1);
    float m0 = 0.f, m1 = 0.f;
#pragma unroll
    for (int nt = 0; nt < 4; nt++) {
        int cj = j0 + wn * 32 + nt * 8 + 2 * t4;
        float nb0 = g_nA[cj];
        float nb1 = g_nA[cj + 1];
        float* dd = dot[nt];
        float d00 = fdist(fmaxf(na0 + nb0 - 2.f * dd[0], 0.f));
        float d01 = fdist(fmaxf(na0 + nb1 - 2.f * dd[1], 0.f));
        float d10 = fdist(fmaxf(na1 + nb0 - 2.f * dd[2], 0.f));
        float d11 = fdist(fmaxf(na1 + nb1 - 2.f * dd[3], 0.f));
        int jm = cj & (B_ - 1);                  // cj even -> pair contiguous
        float2 af0 = *(const float2*)&g_acc[ri * B_ + jm];        // a00,a01
        float2 af1 = *(const float2*)&g_acc[(ri + 8) * B_ + jm];  // a10,a11
        float2 bf0 = *(const float2*)&g_accT[im0 * M_ + cj];      // b00,b01
        float2 bf1 = *(const float2*)&g_accT[im1 * M_ + cj];      // b10,b11
        float2 v0, v1;
        v0.x = sqrtf(af0.x * af0.x + bf0.x * bf0.x + d00 * d00);
        v0.y = sqrtf(af0.y * af0.y + bf0.y * bf0.y + d01 * d01);
        v1.x = sqrtf(af1.x * af1.x + bf1.x * bf1.x + d10 * d10);
        v1.y = sqrtf(af1.y * af1.y + bf1.y * bf1.y + d11 * d11);
        *(float2*)&g_S[(long long)ri * M_ + cj] = v0;
        *(float2*)&g_S[(long long)(ri + 8) * M_ + cj] = v1;
        m0 = fmaxf(m0, fmaxf(v0.x, v0.y));
        m1 = fmaxf(m1, fmaxf(v1.x, v1.y));
    }
    // fold over t4 quad (exact max -> deterministic)
    m0 = fmaxf(m0, __shfl_xor_sync(0xffffffffu, m0, 1));
    m0 = fmaxf(m0, __shfl_xor_sync(0xffffffffu, m0, 2));
    m1 = fmaxf(m1, __shfl_xor_sync(0xffffffffu, m1, 1));
    m1 = fmaxf(m1, __shfl_xor_sync(0xffffffffu, m1, 2));
    if (t4 == 0) {
        atomicMax(&srmax[wm * 16 + g], __float_as_int(m0));
        atomicMax(&srmax[wm * 16 + 8 + g], __float_as_int(m1));
    }
    __syncthreads();
    if (tid < 64) atomicMax(&g_rmax[i0 + tid], srmax[tid]);
}

// ---------------------------------------------------------------------------
// K6: per-row single pass: sumexp over j!=i with precomputed max; pos lookup.
__global__ void __launch_bounds__(256) row_sum() {
    int i = blockIdx.x;
    int tid = threadIdx.x;
    __shared__ float red[256];
    __shared__ float spos;

    float mx = __int_as_float(g_rmax[i]);
    int pos = (i < B_) ? (i + B_) : (i - B_);

    const float4* row4 = (const float4*)(g_S + (long long)i * M_);
    float4 v = row4[tid];
    if (tid == (pos >> 2)) spos = ((const float*)&v)[pos & 3];

    int jb = tid * 4;
    float s = 0.f;
    s += (jb + 0 != i) ? __expf(v.x - mx) : 0.f;
    s += (jb + 1 != i) ? __expf(v.y - mx) : 0.f;
    s += (jb + 2 != i) ? __expf(v.z - mx) : 0.f;
    s += (jb + 3 != i) ? __expf(v.w - mx) : 0.f;

    red[tid] = s;
    __syncthreads();   // orders spos write before the tid==0 read below
    for (int st = 128; st > 0; st >>= 1) {
        if (tid < st) red[tid] += red[tid + st];
        __syncthreads();
    }
    if (tid == 0) {
        float log_prob = (spos - mx) - logf(red[0]);
        g_loss[i] = -log_prob;
    }
}

// K7: final mean
__global__ void __launch_bounds__(256) final_reduce(float* __restrict__ out) {
    int tid = threadIdx.x;
    __shared__ float red[256];
    float s = 0.f;
    for (int j = tid; j < M_; j += 256) s += g_loss[j];
    red[tid] = s;
    __syncthreads();
    for (int st = 128; st > 0; st >>= 1) {
        if (tid < st) red[tid] += red[tid + st];
        __syncthreads();
    }
    if (tid == 0) out[0] = red[0] * (1.f / (float)M_);
}

// ---------------------------------------------------------------------------
extern "C" void kernel_launch(void* const* d_in, const int* in_sizes, int n_in,
                              void* d_out, int out_size) {
    const float* features = (const float*)d_in[0];   // (512, 2, 128) f32
    const int*   indices  = (const int*)d_in[1];     // (512,) i32
    const float* saved    = (const float*)d_in[2];   // (100000, 128) f32
    const int*   rks      = (const int*)d_in[3];     // (100000, 50) i32
    float* out = (float*)d_out;

    build_anchor<<<M_, D_>>>(features);
    gather_neigh<<<K_ * B_, D_>>>(saved, indices, rks);
    pk_all<<<dim3(B_ / 64, M_ / 64), 256>>>();
    s_fused<<<dim3(M_ / 64, M_ / 64), 256>>>();
    row_sum<<<M_, 256>>>();
    final_reduce<<<1, 256>>>(out);
}

// round 9
// speedup vs baseline: 3.1657x; 1.1674x over previous
#include <cuda_runtime.h>
#include <math.h>

// Problem constants
#define B_   512
#define V_   2
#define D_   128
#define M_   1024          // V*B
#define K_   15            // TOP_K
#define KMAX 50
#define INV_T 14.285714285714286f   // 1/0.07

// Scratch (static device globals)
__device__ unsigned g_Abf[M_ * 64];        // anchors packed bf16x2 [i][d/2]
__device__ unsigned g_Gbf[K_ * B_ * 64];   // neighbors packed bf16x2
__device__ float g_nA[M_];                 // ||A_i||^2 (fp32 exact)
__device__ float g_nG[K_ * B_];            // ||G_r||^2
__device__ float g_accp[2][M_ * B_];       // partial k-sums [grp][i][b]
__device__ float g_accpT[2][B_ * M_];      // partial k-sums transposed
__device__ float g_S[M_ * M_];             // logits_src
__device__ int   g_rmax[M_];               // per-row max (float bits, >0)
__device__ float g_loss[M_];               // per-row loss

// ---------------------------------------------------------------------------
__device__ __forceinline__ unsigned pack_bf(float lo, float hi) {
    unsigned r;
    asm("cvt.rn.bf16x2.f32 %0, %1, %2;" : "=r"(r) : "f"(hi), "f"(lo));
    return r;
}
__device__ __forceinline__ float rsq_ap(float x) {
    float r; asm("rsqrt.approx.f32 %0, %1;" : "=f"(r) : "f"(x)); return r;
}
__device__ __forceinline__ float rcp_ap(float x) {
    float r; asm("rcp.approx.f32 %0, %1;" : "=f"(r) : "f"(x)); return r;
}
__device__ __forceinline__ float fdist(float sq) {
    float d = (sq > 0.f) ? sq * rsq_ap(sq) : 0.f;   // sqrt(sq) via rsqrt
    return (1.f + rcp_ap(1.f + d)) * INV_T;
}
__device__ __forceinline__ void mma_bf16(float c[4], const unsigned a[4],
                                         unsigned b0, unsigned b1) {
    asm volatile(
        "mma.sync.aligned.m16n8k16.row.col.f32.bf16.bf16.f32 "
        "{%0,%1,%2,%3}, {%4,%5,%6,%7}, {%8,%9}, {%0,%1,%2,%3};\n"
        : "+f"(c[0]), "+f"(c[1]), "+f"(c[2]), "+f"(c[3])
        : "r"(a[0]), "r"(a[1]), "r"(a[2]), "r"(a[3]), "r"(b0), "r"(b1));
}
__device__ __forceinline__ void ldsm_x4(unsigned r[4], unsigned addr) {
    asm volatile(
        "ldmatrix.sync.aligned.m8n8.x4.shared.b16 {%0,%1,%2,%3}, [%4];"
        : "=r"(r[0]), "=r"(r[1]), "=r"(r[2]), "=r"(r[3]) : "r"(addr));
}
__device__ __forceinline__ unsigned sm_u32(const void* p) {
    return (unsigned)__cvta_generic_to_shared(p);
}

// ---------------------------------------------------------------------------
// K1: anchors -> bf16 pack + exact fp32 norms, warp-per-row; reset g_rmax.
__global__ void __launch_bounds__(256) build_anchor(const float* __restrict__ features) {
    int w = threadIdx.x >> 5;            // warp in block
    int lane = threadIdx.x & 31;
    int i = blockIdx.x * 8 + w;          // row 0..M_-1
    int v = i >> 9;
    int b = i & (B_ - 1);
    float4 val = *(const float4*)&features[(b * V_ + v) * D_ + lane * 4];
    float s = val.x * val.x + val.y * val.y + val.z * val.z + val.w * val.w;
#pragma unroll
    for (int st = 16; st > 0; st >>= 1)
        s += __shfl_xor_sync(0xffffffffu, s, st);
    *(uint2*)&g_Abf[i * 64 + lane * 2] =
        make_uint2(pack_bf(val.x, val.y), pack_bf(val.z, val.w));
    if (lane == 0) { g_nA[i] = s; g_rmax[i] = 0; }
}

// K2: gather neighbors -> bf16 pack + norms, warp-per-row.
__global__ void __launch_bounds__(256) gather_neigh(const float* __restrict__ saved,
                             const int* __restrict__ indices,
                             const int* __restrict__ rks) {
    int w = threadIdx.x >> 5;
    int lane = threadIdx.x & 31;
    int r = blockIdx.x * 8 + w;          // 0..K_*B_-1
    int k = r / B_;
    int b = r - k * B_;
    int idx = rks[indices[b] * KMAX + k];
    float4 val = *(const float4*)&saved[(long long)idx * D_ + lane * 4];
    float s = val.x * val.x + val.y * val.y + val.z * val.z + val.w * val.w;
#pragma unroll
    for (int st = 16; st > 0; st >>= 1)
        s += __shfl_xor_sync(0xffffffffu, s, st);
    *(uint2*)&g_Gbf[r * 64 + lane * 2] =
        make_uint2(pack_bf(val.x, val.y), pack_bf(val.z, val.w));
    if (lane == 0) g_nG[r] = s;
}

// ---------------------------------------------------------------------------
// K3: partial accB over a k-group. Tile 64(i) x 64(b), grid z = 2 k-groups.
// 256 thr = 8 warps (4m x 2n), warp tile 16x32. ldmatrix + double buffer.
__global__ void __launch_bounds__(256, 2) pk_all() {
    __shared__ unsigned As[64 * 64];
    __shared__ unsigned Bs[2][64 * 64];

    int grp = blockIdx.z;
    int k0 = grp * 8;
    int kend = (grp == 0) ? 8 : K_;
    int i0 = blockIdx.y * 64;
    int b0 = blockIdx.x * 64;
    int tid = threadIdx.x;
    int lane = tid & 31, warp = tid >> 5;
    int wm = warp >> 1, wn = warp & 1;
    int g = lane >> 2, t4 = lane & 3;
    int l7 = lane & 7;

    // Fill A tile once (full D)
#pragma unroll
    for (int q = 0; q < 4; q++) {
        int idx = q * 256 + tid;
        int row = idx >> 4, c4 = idx & 15;
        uint4 v = *(const uint4*)&g_Abf[(i0 + row) * 64 + c4 * 4];
        *(uint4*)&As[row * 64 + ((c4 * 4) ^ ((row & 7) << 2))] = v;
    }

    // ldmatrix lane addressing (byte offsets; row stride 64 words = 256 B)
    unsigned swl = l7 << 2;
    unsigned aBase = sm_u32(As) + (wm * 16 + (lane & 15)) * 256;
    unsigned koA = (lane >> 4) << 2;
    unsigned bRow0 = wn * 32 + ((lane >> 4) & 1) * 8 + l7;
    unsigned koB = ((lane >> 3) & 1) << 2;
    unsigned bBase0 = sm_u32(Bs) + bRow0 * 256;
    unsigned bBase1 = bBase0 + 16 * 256;

    float fsum[4][4];
#pragma unroll
    for (int nt = 0; nt < 4; nt++)
#pragma unroll
        for (int q = 0; q < 4; q++) fsum[nt][q] = 0.f;

    // prefetch first B tile into registers
    uint4 pre[4];
    {
        const unsigned* Gb = g_Gbf + (k0 * B_ + b0) * 64;
#pragma unroll
        for (int q = 0; q < 4; q++) {
            int idx = q * 256 + tid;
            int row = idx >> 4, c4 = idx & 15;
            pre[q] = *(const uint4*)&Gb[row * 64 + c4 * 4];
        }
    }

    int cur = 0;
#pragma unroll 1
    for (int k = k0; k < kend; k++) {
        // store prefetched tile
#pragma unroll
        for (int q = 0; q < 4; q++) {
            int idx = q * 256 + tid;
            int row = idx >> 4, c4 = idx & 15;
            *(uint4*)&Bs[cur][row * 64 + ((c4 * 4) ^ ((row & 7) << 2))] = pre[q];
        }
        __syncthreads();

        // prefetch next k
        if (k + 1 < kend) {
            const unsigned* Gb = g_Gbf + ((k + 1) * B_ + b0) * 64;
#pragma unroll
            for (int q = 0; q < 4; q++) {
                int idx = q * 256 + tid;
                int row = idx >> 4, c4 = idx & 15;
                pre[q] = *(const uint4*)&Gb[row * 64 + c4 * 4];
            }
        }

        float dot[4][4];
#pragma unroll
        for (int nt = 0; nt < 4; nt++)
#pragma unroll
            for (int q = 0; q < 4; q++) dot[nt][q] = 0.f;

        unsigned bcur = (unsigned)(cur * (64 * 64 * 4));
#pragma unroll
        for (int s = 0; s < 8; s++) {
            unsigned a[4], bb0[4], bb1[4];
            ldsm_x4(a, aBase + ((((unsigned)(s * 8) + koA) ^ swl) << 2));
            ldsm_x4(bb0, bBase0 + bcur + ((((unsigned)(s * 8) + koB) ^ swl) << 2));
            ldsm_x4(bb1, bBase1 + bcur + ((((unsigned)(s * 8) + koB) ^ swl) << 2));
            mma_bf16(dot[0], a, bb0[0], bb0[1]);
            mma_bf16(dot[1], a, bb0[2], bb0[3]);
            mma_bf16(dot[2], a, bb1[0], bb1[1]);
            mma_bf16(dot[3], a, bb1[2], bb1[3]);
        }

        // fold f(dist) for this k
        int ri = i0 + wm * 16 + g;
        float na0 = g_nA[ri];
        float na1 = g_nA[ri + 8];
#pragma unroll
        for (int nt = 0; nt < 4; nt++) {
            int cb = b0 + wn * 32 + nt * 8 + 2 * t4;
            float ng0 = g_nG[k * B_ + cb];
            float ng1 = g_nG[k * B_ + cb + 1];
            float* dd = dot[nt];
            fsum[nt][0] += fdist(fmaxf(na0 + ng0 - 2.f * dd[0], 0.f));
            fsum[nt][1] += fdist(fmaxf(na0 + ng1 - 2.f * dd[1], 0.f));
            fsum[nt][2] += fdist(fmaxf(na1 + ng0 - 2.f * dd[2], 0.f));
            fsum[nt][3] += fdist(fmaxf(na1 + ng1 - 2.f * dd[3], 0.f));
        }
        cur ^= 1;
    }

    float* P  = g_accp[grp];
    float* PT = g_accpT[grp];
    int ri = i0 + wm * 16 + g;
#pragma unroll
    for (int nt = 0; nt < 4; nt++) {
        int cb = b0 + wn * 32 + nt * 8 + 2 * t4;
        *(float2*)&P[ri * B_ + cb] = make_float2(fsum[nt][0], fsum[nt][1]);
        *(float2*)&P[(ri + 8) * B_ + cb] = make_float2(fsum[nt][2], fsum[nt][3]);
        PT[cb * M_ + ri] = fsum[nt][0];
        PT[(cb + 1) * M_ + ri] = fsum[nt][1];
        PT[cb * M_ + ri + 8] = fsum[nt][2];
        PT[(cb + 1) * M_ + ri + 8] = fsum[nt][3];
    }
}

// ---------------------------------------------------------------------------
// K5: S[i][j] = sqrt(acc[i][j%B]^2 + acc[j][i%B]^2 + f(dist)^2); plus row max.
// acc = (partial0 + partial1) / 15, combined inline.
__global__ void __launch_bounds__(256, 2) s_fused() {
    __shared__ unsigned As[64 * 64];
    __shared__ unsigned Bs[64 * 64];
    __shared__ int srmax[64];

    int i0 = blockIdx.y * 64;
    int j0 = blockIdx.x * 64;
    int tid = threadIdx.x;
    int lane = tid & 31, warp = tid >> 5;
    int wm = warp >> 1, wn = warp & 1;
    int g = lane >> 2, t4 = lane & 3;
    int l7 = lane & 7;

#pragma unroll
    for (int q = 0; q < 4; q++) {
        int idx = q * 256 + tid;
        int row = idx >> 4, c4 = idx & 15;
        uint4 va = *(const uint4*)&g_Abf[(i0 + row) * 64 + c4 * 4];
        *(uint4*)&As[row * 64 + ((c4 * 4) ^ ((row & 7) << 2))] = va;
        uint4 vb = *(const uint4*)&g_Abf[(j0 + row) * 64 + c4 * 4];
        *(uint4*)&Bs[row * 64 + ((c4 * 4) ^ ((row & 7) << 2))] = vb;
    }
    if (tid < 64) srmax[tid] = 0;
    __syncthreads();

    unsigned swl = l7 << 2;
    unsigned aBase = sm_u32(As) + (wm * 16 + (lane & 15)) * 256;
    unsigned koA = (lane >> 4) << 2;
    unsigned bRow0 = wn * 32 + ((lane >> 4) & 1) * 8 + l7;
    unsigned koB = ((lane >> 3) & 1) << 2;
    unsigned bBase0 = sm_u32(Bs) + bRow0 * 256;
    unsigned bBase1 = bBase0 + 16 * 256;

    float dot[4][4];
#pragma unroll
    for (int nt = 0; nt < 4; nt++)
#pragma unroll
        for (int q = 0; q < 4; q++) dot[nt][q] = 0.f;

#pragma unroll
    for (int s = 0; s < 8; s++) {
        unsigned a[4], bb0[4], bb1[4];
        ldsm_x4(a, aBase + ((((unsigned)(s * 8) + koA) ^ swl) << 2));
        ldsm_x4(bb0, bBase0 + ((((unsigned)(s * 8) + koB) ^ swl) << 2));
        ldsm_x4(bb1, bBase1 + ((((unsigned)(s * 8) + koB) ^ swl) << 2));
        mma_bf16(dot[0], a, bb0[0], bb0[1]);
        mma_bf16(dot[1], a, bb0[2], bb0[3]);
        mma_bf16(dot[2], a, bb1[0], bb1[1]);
        mma_bf16(dot[3], a, bb1[2], bb1[3]);
    }

    const float inv = 1.f / (float)K_;
    int ri = i0 + wm * 16 + g;
    float na0 = g_nA[ri];
    float na1 = g_nA[ri + 8];
    int im0 = ri & (B_ - 1);
    int im1 = (ri + 8) & (B_ - 1);
    float m0 = 0.f, m1 = 0.f;
#pragma unroll
    for (int nt = 0; nt < 4; nt++) {
        int cj = j0 + wn * 32 + nt * 8 + 2 * t4;
        float nb0 = g_nA[cj];
        float nb1 = g_nA[cj + 1];
        float* dd = dot[nt];
        float d00 = fdist(fmaxf(na0 + nb0 - 2.f * dd[0], 0.f));
        float d01 = fdist(fmaxf(na0 + nb1 - 2.f * dd[1], 0.f));
        float d10 = fdist(fmaxf(na1 + nb0 - 2.f * dd[2], 0.f));
        float d11 = fdist(fmaxf(na1 + nb1 - 2.f * dd[3], 0.f));
        int jm = cj & (B_ - 1);                  // cj even -> pair contiguous
        float2 afa0 = *(const float2*)&g_accp[0][ri * B_ + jm];
        float2 afb0 = *(const float2*)&g_accp[1][ri * B_ + jm];
        float2 afa1 = *(const float2*)&g_accp[0][(ri + 8) * B_ + jm];
        float2 afb1 = *(const float2*)&g_accp[1][(ri + 8) * B_ + jm];
        float2 bfa0 = *(const float2*)&g_accpT[0][im0 * M_ + cj];
        float2 bfb0 = *(const float2*)&g_accpT[1][im0 * M_ + cj];
        float2 bfa1 = *(const float2*)&g_accpT[0][im1 * M_ + cj];
        float2 bfb1 = *(const float2*)&g_accpT[1][im1 * M_ + cj];
        float a00 = (afa0.x + afb0.x) * inv, a01 = (afa0.y + afb0.y) * inv;
        float a10 = (afa1.x + afb1.x) * inv, a11 = (afa1.y + afb1.y) * inv;
        float b00 = (bfa0.x + bfb0.x) * inv, b01 = (bfa0.y + bfb0.y) * inv;
        float b10 = (bfa1.x + bfb1.x) * inv, b11 = (bfa1.y + bfb1.y) * inv;
        float2 v0, v1;
        v0.x = sqrtf(a00 * a00 + b00 * b00 + d00 * d00);
        v0.y = sqrtf(a01 * a01 + b01 * b01 + d01 * d01);
        v1.x = sqrtf(a10 * a10 + b10 * b10 + d10 * d10);
        v1.y = sqrtf(a11 * a11 + b11 * b11 + d11 * d11);
        *(float2*)&g_S[(long long)ri * M_ + cj] = v0;
        *(float2*)&g_S[(long long)(ri + 8) * M_ + cj] = v1;
        m0 = fmaxf(m0, fmaxf(v0.x, v0.y));
        m1 = fmaxf(m1, fmaxf(v1.x, v1.y));
    }
    // fold over t4 quad (exact max -> deterministic)
    m0 = fmaxf(m0, __shfl_xor_sync(0xffffffffu, m0, 1));
    m0 = fmaxf(m0, __shfl_xor_sync(0xffffffffu, m0, 2));
    m1 = fmaxf(m1, __shfl_xor_sync(0xffffffffu, m1, 1));
    m1 = fmaxf(m1, __shfl_xor_sync(0xffffffffu, m1, 2));
    if (t4 == 0) {
        atomicMax(&srmax[wm * 16 + g], __float_as_int(m0));
        atomicMax(&srmax[wm * 16 + 8 + g], __float_as_int(m1));
    }
    __syncthreads();
    if (tid < 64) atomicMax(&g_rmax[i0 + tid], srmax[tid]);
}

// ---------------------------------------------------------------------------
// K6: per-row single pass: sumexp over j!=i with precomputed max; pos lookup.
__global__ void __launch_bounds__(256) row_sum() {
    int i = blockIdx.x;
    int tid = threadIdx.x;
    __shared__ float red[256];
    __shared__ float spos;

    float mx = __int_as_float(g_rmax[i]);
    int pos = (i < B_) ? (i + B_) : (i - B_);

    const float4* row4 = (const float4*)(g_S + (long long)i * M_);
    float4 v = row4[tid];
    if (tid == (pos >> 2)) spos = ((const float*)&v)[pos & 3];

    int jb = tid * 4;
    float s = 0.f;
    s += (jb + 0 != i) ? __expf(v.x - mx) : 0.f;
    s += (jb + 1 != i) ? __expf(v.y - mx) : 0.f;
    s += (jb + 2 != i) ? __expf(v.z - mx) : 0.f;
    s += (jb + 3 != i) ? __expf(v.w - mx) : 0.f;

    red[tid] = s;
    __syncthreads();   // orders spos write before the tid==0 read below
    for (int st = 128; st > 0; st >>= 1) {
        if (tid < st) red[tid] += red[tid + st];
        __syncthreads();
    }
    if (tid == 0) {
        float log_prob = (spos - mx) - logf(red[0]);
        g_loss[i] = -log_prob;
    }
}

// K7: final mean
__global__ void __launch_bounds__(256) final_reduce(float* __restrict__ out) {
    int tid = threadIdx.x;
    __shared__ float red[256];
    float s = 0.f;
    for (int j = tid; j < M_; j += 256) s += g_loss[j];
    red[tid] = s;
    __syncthreads();
    for (int st = 128; st > 0; st >>= 1) {
        if (tid < st) red[tid] += red[tid + st];
        __syncthreads();
    }
    if (tid == 0) out[0] = red[0] * (1.f / (float)M_);
}

// ---------------------------------------------------------------------------
extern "C" void kernel_launch(void* const* d_in, const int* in_sizes, int n_in,
                              void* d_out, int out_size) {
    const float* features = (const float*)d_in[0];   // (512, 2, 128) f32
    const int*   indices  = (const int*)d_in[1];     // (512,) i32
    const float* saved    = (const float*)d_in[2];   // (100000, 128) f32
    const int*   rks      = (const int*)d_in[3];     // (100000, 50) i32
    float* out = (float*)d_out;

    build_anchor<<<M_ / 8, 256>>>(features);
    gather_neigh<<<(K_ * B_) / 8, 256>>>(saved, indices, rks);
    pk_all<<<dim3(B_ / 64, M_ / 64, 2), 256>>>();
    s_fused<<<dim3(M_ / 64, M_ / 64), 256>>>();
    row_sum<<<M_, 256>>>();
    final_reduce<<<1, 256>>>(out);
}